// round 8
// baseline (speedup 1.0000x reference)
#include <cuda_runtime.h>
#include <cstdint>

#define N_NODES 500000
#define N_EDGES 8000000

// scan geometry: 256 threads x 8 items = 2048 per block
#define SC_BLK   256
#define SC_ITEMS 8
#define SC_CHUNK 2048
#define SC_NB    ((N_NODES + SC_CHUNK - 1) / SC_CHUNK)   // 245

// ---------------- scratch (device globals: allocation-free) ----------------
__device__ __align__(16) float4 g_xs  [N_NODES];    // x * dinv (pad), 8 MB, L2-resident
__device__ __align__(8)  float  g_hs2 [N_NODES*2];  // layer-2 scaled features, 4 MB
__device__               float  g_dinv[N_NODES];
__device__               int    g_cnt [N_NODES];    // dst histogram (self-cleaning: zeroed in k_node1)
__device__               int    g_cur [N_NODES];    // scan result -> scatter cursor -> row-end offsets
__device__               int    g_bsum[SC_NB];      // per-block partials for scan
__device__               int    g_csr [N_EDGES];    // src indices sorted by dst

// ---------------- kernels ----------------

// dst histogram, 4 edges/thread (g_cnt starts 0: bss on first call, reset by k_node1 after)
__global__ void k_hist(const int* __restrict__ ei) {
    int i = blockIdx.x * blockDim.x + threadIdx.x;
    if (i >= N_EDGES / 4) return;
    int4 d4 = __ldg(reinterpret_cast<const int4*>(ei + N_EDGES) + i);
    atomicAdd(&g_cnt[d4.x], 1);
    atomicAdd(&g_cnt[d4.y], 1);
    atomicAdd(&g_cnt[d4.z], 1);
    atomicAdd(&g_cnt[d4.w], 1);
}

// exclusive scan, stage 1: per-block scan of 2048 counts -> g_cur, block total -> g_bsum
__global__ void k_scan1() {
    __shared__ int wsum[SC_BLK / 32];
    int b = blockIdx.x, t = threadIdx.x;
    int base = b * SC_CHUNK + t * SC_ITEMS;
    int v[SC_ITEMS], p[SC_ITEMS];
    int s = 0;
#pragma unroll
    for (int j = 0; j < SC_ITEMS; j++) {
        int idx = base + j;
        v[j] = (idx < N_NODES) ? g_cnt[idx] : 0;
        p[j] = s;
        s += v[j];
    }
    int lane = t & 31, wid = t >> 5;
    int inc = s;
#pragma unroll
    for (int o = 1; o < 32; o <<= 1) {
        int n = __shfl_up_sync(0xffffffffu, inc, o);
        if (lane >= o) inc += n;
    }
    int wexcl = inc - s;
    if (lane == 31) wsum[wid] = inc;
    __syncthreads();
    if (t < SC_BLK / 32) {
        int ws = wsum[t];
        int in = ws;
#pragma unroll
        for (int o = 1; o < SC_BLK / 32; o <<= 1) {
            int n = __shfl_up_sync((1u << (SC_BLK / 32)) - 1u, in, o);
            if (t >= o) in += n;
        }
        wsum[t] = in - ws;
    }
    __syncthreads();
    int tex = wexcl + wsum[wid];
#pragma unroll
    for (int j = 0; j < SC_ITEMS; j++) {
        int idx = base + j;
        if (idx < N_NODES) g_cur[idx] = tex + p[j];
    }
    if (t == SC_BLK - 1) g_bsum[b] = tex + s;
}

// stage 2: scan the 245 block totals (one block)
__global__ void k_scan2() {
    __shared__ int sm[256];
    int t = threadIdx.x;
    int v = (t < SC_NB) ? g_bsum[t] : 0;
    sm[t] = v;
    __syncthreads();
    for (int o = 1; o < 256; o <<= 1) {
        int x = (t >= o) ? sm[t - o] : 0;
        __syncthreads();
        sm[t] += x;
        __syncthreads();
    }
    if (t < SC_NB) g_bsum[t] = sm[t] - v;   // exclusive
}

// stage 3: add block offsets -> g_cur holds final exclusive row-start offsets
__global__ void k_scan3() {
    int i = blockIdx.x * blockDim.x + threadIdx.x;
    if (i < N_NODES) g_cur[i] += g_bsum[i >> 11];   // 2048 = 1<<11
}

// dinv = rsqrt(cnt + 1 self-loop); xs = x*dinv; reset g_cnt for next call
__global__ void k_node1(const float* __restrict__ x) {
    int i = blockIdx.x * blockDim.x + threadIdx.x;
    if (i >= N_NODES) return;
    float dv = rsqrtf((float)g_cnt[i] + 1.0f);
    g_cnt[i] = 0;                                   // self-cleaning for graph replay
    g_dinv[i] = dv;
    float x0 = x[3 * i], x1 = x[3 * i + 1], x2 = x[3 * i + 2];
    g_xs[i] = make_float4(x0 * dv, x1 * dv, x2 * dv, 0.f);
}

// scatter edges into CSR: csr[cur[dst]++] = src.  After this, g_cur[d] == row_end(d).
__global__ void k_scatter(const int* __restrict__ ei) {
    int i = blockIdx.x * blockDim.x + threadIdx.x;
    if (i >= N_EDGES / 4) return;
    int4 s4 = __ldg(reinterpret_cast<const int4*>(ei) + i);
    int4 d4 = __ldg(reinterpret_cast<const int4*>(ei + N_EDGES) + i);
    g_csr[atomicAdd(&g_cur[d4.x], 1)] = s4.x;
    g_csr[atomicAdd(&g_cur[d4.y], 1)] = s4.y;
    g_csr[atomicAdd(&g_cur[d4.z], 1)] = s4.z;
    g_csr[atomicAdd(&g_cur[d4.w], 1)] = s4.w;
}

// layer-1 aggregation (atomic-free) fused with MLP: hs2 = (relu(dinv*(Σxs)@W1+b1)@W2)*dinv
__global__ void k_agg1(const float* __restrict__ W1, const float* __restrict__ b1,
                       const float* __restrict__ W2) {
    int d = blockIdx.x * blockDim.x + threadIdx.x;
    if (d >= N_NODES) return;
    int beg = d ? __ldg(&g_cur[d - 1]) : 0;     // row_end(d-1) == row_start(d)
    int end = __ldg(&g_cur[d]);
    float dv = g_dinv[d];
    float4 self = g_xs[d];
    float ax = self.x, ay = self.y, az = self.z;
    float bx = 0.f, by = 0.f, bz = 0.f;
    int e = beg;
    for (; e + 1 < end; e += 2) {               // 2-way ILP
        int s0 = __ldg(&g_csr[e]);
        int s1 = __ldg(&g_csr[e + 1]);
        float4 u = __ldg(&g_xs[s0]);
        float4 w = __ldg(&g_xs[s1]);
        ax += u.x; ay += u.y; az += u.z;
        bx += w.x; by += w.y; bz += w.z;
    }
    if (e < end) {
        float4 u = __ldg(&g_xs[__ldg(&g_csr[e])]);
        ax += u.x; ay += u.y; az += u.z;
    }
    float t0 = dv * (ax + bx), t1 = dv * (ay + by), t2 = dv * (az + bz);
    float a[8];
#pragma unroll
    for (int j = 0; j < 8; j++) {
        float v = t0 * __ldg(&W1[j]) + t1 * __ldg(&W1[8 + j]) + t2 * __ldg(&W1[16 + j])
                  + __ldg(&b1[j]);
        a[j] = fmaxf(v, 0.0f);
    }
    float o0 = 0.f, o1 = 0.f;
#pragma unroll
    for (int j = 0; j < 8; j++) {
        o0 += a[j] * __ldg(&W2[2 * j]);
        o1 += a[j] * __ldg(&W2[2 * j + 1]);
    }
    reinterpret_cast<float2*>(&g_hs2[(size_t)d * 2])[0] = make_float2(o0 * dv, o1 * dv);
}

// layer-2 aggregation (atomic-free) fused with finalize: out = dinv*Σhs2 + b2 (single write)
__global__ void k_agg2(const float* __restrict__ b2, float* __restrict__ out) {
    int d = blockIdx.x * blockDim.x + threadIdx.x;
    if (d >= N_NODES) return;
    int beg = d ? __ldg(&g_cur[d - 1]) : 0;
    int end = __ldg(&g_cur[d]);
    float dv = g_dinv[d];
    const float2* hs = reinterpret_cast<const float2*>(g_hs2);
    float2 self = hs[d];
    float ox = self.x, oy = self.y;
    float px = 0.f, py = 0.f;
    int e = beg;
    for (; e + 1 < end; e += 2) {
        int s0 = __ldg(&g_csr[e]);
        int s1 = __ldg(&g_csr[e + 1]);
        float2 u = __ldg(hs + s0);
        float2 w = __ldg(hs + s1);
        ox += u.x; oy += u.y;
        px += w.x; py += w.y;
    }
    if (e < end) {
        float2 u = __ldg(hs + __ldg(&g_csr[e]));
        ox += u.x; oy += u.y;
    }
    reinterpret_cast<float2*>(&out[(size_t)d * 2])[0] =
        make_float2(dv * (ox + px) + __ldg(&b2[0]),
                    dv * (oy + py) + __ldg(&b2[1]));
}

// ---------------- launch ----------------
extern "C" void kernel_launch(void* const* d_in, const int* in_sizes, int n_in,
                              void* d_out, int out_size) {
    const float* x  = (const float*)d_in[0];   // [N, 3] f32
    const int*   ei = (const int*)d_in[1];     // [2, E] int32
    const float* W1 = (const float*)d_in[2];   // [3, 8]
    const float* b1 = (const float*)d_in[3];   // [8]
    const float* W2 = (const float*)d_in[4];   // [8, 2]
    const float* b2 = (const float*)d_in[5];   // [2]
    float* out = (float*)d_out;                // [N, 2] f32

    const int TB = 256;
    const int gN  = (N_NODES + TB - 1) / TB;
    const int gE4 = (N_EDGES / 4 + TB - 1) / TB;

    k_hist   <<<gE4, TB>>>(ei);
    k_scan1  <<<SC_NB, SC_BLK>>>();
    k_scan2  <<<1, 256>>>();
    k_scan3  <<<gN, TB>>>();
    k_node1  <<<gN, TB>>>(x);      // also resets g_cnt for next replay
    k_scatter<<<gE4, TB>>>(ei);
    k_agg1   <<<gN, TB>>>(W1, b1, W2);
    k_agg2   <<<gN, TB>>>(b2, out);
}

// round 9
// speedup vs baseline: 1.2240x; 1.2240x over previous
#include <cuda_runtime.h>
#include <cstdint>

// Problem constants (from reference_code)
#define N_NODES 500000
#define N_EDGES 8000000

// ---------------- scratch (device globals: allocation-free) ----------------
// Layer-1 aggregation happens in 3-dim input space (linearity of x@W1):
//   out1[d] = dinv[d] * (sum_s xs[s] + xs[d]) @ W1 + b1,  xs = x * dinv
__device__ __align__(16) float4 g_xs  [N_NODES];   // (x*dinv, pad) 8 MB, L2-resident
__device__ __align__(16) float4 g_acc [N_NODES];   // layer-1 scatter accumulator, 8 MB
__device__ __align__(8)  float  g_hs2 [N_NODES*2]; // layer-2 scaled features, 4 MB
__device__               float  g_deg [N_NODES];   // degree (incl. self-loop)
__device__               float  g_dinv[N_NODES];   // rsqrt(deg)

// ---------------- kernels ----------------

__global__ void k_init_deg() {
    int i = blockIdx.x * blockDim.x + threadIdx.x;
    if (i < N_NODES) g_deg[i] = 1.0f;   // self-loop contributes 1
}

// 8 edges per thread, 2x int4 index loads, batched REDs
__global__ void k_degree(const int* __restrict__ ei) {
    int i = blockIdx.x * blockDim.x + threadIdx.x;
    if (i >= N_EDGES / 8) return;
    const int4* dp = reinterpret_cast<const int4*>(ei + N_EDGES) + i * 2;
    int4 a = __ldg(dp);
    int4 b = __ldg(dp + 1);
    atomicAdd(&g_deg[a.x], 1.0f);
    atomicAdd(&g_deg[a.y], 1.0f);
    atomicAdd(&g_deg[a.z], 1.0f);
    atomicAdd(&g_deg[a.w], 1.0f);
    atomicAdd(&g_deg[b.x], 1.0f);
    atomicAdd(&g_deg[b.y], 1.0f);
    atomicAdd(&g_deg[b.z], 1.0f);
    atomicAdd(&g_deg[b.w], 1.0f);
}

// dinv = rsqrt(deg); xs = x * dinv (3-vec in float4); acc = 0
__global__ void k_node1(const float* __restrict__ x) {
    int i = blockIdx.x * blockDim.x + threadIdx.x;
    if (i >= N_NODES) return;
    float dv = rsqrtf(g_deg[i]);
    g_dinv[i] = dv;
    float x0 = x[3 * i], x1 = x[3 * i + 1], x2 = x[3 * i + 2];
    g_xs [i] = make_float4(x0 * dv, x1 * dv, x2 * dv, 0.f);
    g_acc[i] = make_float4(0.f, 0.f, 0.f, 0.f);
}

#define RED4(ptr, v) \
    asm volatile("red.global.add.v4.f32 [%0], {%1,%2,%3,%4};" \
                 :: "l"(ptr), "f"((v).x), "f"((v).y), "f"((v).z), "f"((v).w) : "memory")
#define RED2(ptr, v) \
    asm volatile("red.global.add.v2.f32 [%0], {%1,%2};" \
                 :: "l"(ptr), "f"((v).x), "f"((v).y) : "memory")

// acc[dst] += xs[src]; 8 edges/thread, all gathers issued before all REDs (MLP=8)
__global__ void k_edge1(const int* __restrict__ ei) {
    int i = blockIdx.x * blockDim.x + threadIdx.x;
    if (i >= N_EDGES / 8) return;
    const int4* sp = reinterpret_cast<const int4*>(ei) + i * 2;
    const int4* dp = reinterpret_cast<const int4*>(ei + N_EDGES) + i * 2;
    int4 s0 = __ldg(sp), s1 = __ldg(sp + 1);
    int4 d0 = __ldg(dp), d1 = __ldg(dp + 1);
    float4 v0 = __ldg(&g_xs[s0.x]);
    float4 v1 = __ldg(&g_xs[s0.y]);
    float4 v2 = __ldg(&g_xs[s0.z]);
    float4 v3 = __ldg(&g_xs[s0.w]);
    float4 v4 = __ldg(&g_xs[s1.x]);
    float4 v5 = __ldg(&g_xs[s1.y]);
    float4 v6 = __ldg(&g_xs[s1.z]);
    float4 v7 = __ldg(&g_xs[s1.w]);
    RED4(&g_acc[d0.x], v0);
    RED4(&g_acc[d0.y], v1);
    RED4(&g_acc[d0.z], v2);
    RED4(&g_acc[d0.w], v3);
    RED4(&g_acc[d1.x], v4);
    RED4(&g_acc[d1.y], v5);
    RED4(&g_acc[d1.z], v6);
    RED4(&g_acc[d1.w], v7);
}

// t = dinv*(acc + xs)  (3-vec);  a = relu(t @ W1 + b1);  hs2 = (a @ W2) * dinv;  out = 0
__global__ void k_node2(const float* __restrict__ W1, const float* __restrict__ b1,
                        const float* __restrict__ W2, float* __restrict__ out) {
    int i = blockIdx.x * blockDim.x + threadIdx.x;
    if (i >= N_NODES) return;
    float dv = g_dinv[i];
    float4 xs = g_xs[i];
    float4 ac = g_acc[i];
    float t0 = dv * (ac.x + xs.x);
    float t1 = dv * (ac.y + xs.y);
    float t2 = dv * (ac.z + xs.z);
    float a[8];
#pragma unroll
    for (int j = 0; j < 8; j++) {
        float v = t0 * __ldg(&W1[j]) + t1 * __ldg(&W1[8 + j]) + t2 * __ldg(&W1[16 + j])
                  + __ldg(&b1[j]);
        a[j] = fmaxf(v, 0.0f);
    }
    float o0 = 0.f, o1 = 0.f;
#pragma unroll
    for (int j = 0; j < 8; j++) {
        o0 += a[j] * __ldg(&W2[2 * j]);
        o1 += a[j] * __ldg(&W2[2 * j + 1]);
    }
    reinterpret_cast<float2*>(&g_hs2[(size_t)i * 2])[0] = make_float2(o0 * dv, o1 * dv);
    reinterpret_cast<float2*>(&out[(size_t)i * 2])[0]   = make_float2(0.f, 0.f);
}

// out[dst] += hs2[src]; 8 edges/thread, batched
__global__ void k_edge2(const int* __restrict__ ei, float* __restrict__ out) {
    int i = blockIdx.x * blockDim.x + threadIdx.x;
    if (i >= N_EDGES / 8) return;
    const int4* sp = reinterpret_cast<const int4*>(ei) + i * 2;
    const int4* dp = reinterpret_cast<const int4*>(ei + N_EDGES) + i * 2;
    int4 s0 = __ldg(sp), s1 = __ldg(sp + 1);
    int4 d0 = __ldg(dp), d1 = __ldg(dp + 1);
    const float2* hs = reinterpret_cast<const float2*>(g_hs2);
    float2 v0 = __ldg(hs + s0.x);
    float2 v1 = __ldg(hs + s0.y);
    float2 v2 = __ldg(hs + s0.z);
    float2 v3 = __ldg(hs + s0.w);
    float2 v4 = __ldg(hs + s1.x);
    float2 v5 = __ldg(hs + s1.y);
    float2 v6 = __ldg(hs + s1.z);
    float2 v7 = __ldg(hs + s1.w);
    RED2(out + (size_t)d0.x * 2, v0);
    RED2(out + (size_t)d0.y * 2, v1);
    RED2(out + (size_t)d0.z * 2, v2);
    RED2(out + (size_t)d0.w * 2, v3);
    RED2(out + (size_t)d1.x * 2, v4);
    RED2(out + (size_t)d1.y * 2, v5);
    RED2(out + (size_t)d1.z * 2, v6);
    RED2(out + (size_t)d1.w * 2, v7);
}

// out = dinv*(out + hs2) + b2
__global__ void k_fin(const float* __restrict__ b2, float* __restrict__ out) {
    int i = blockIdx.x * blockDim.x + threadIdx.x;
    if (i >= N_NODES) return;
    float dv = g_dinv[i];
    float2* op = reinterpret_cast<float2*>(&out[(size_t)i * 2]);
    float2 acc = op[0];
    const float2 h = reinterpret_cast<const float2*>(&g_hs2[(size_t)i * 2])[0];
    op[0] = make_float2(dv * (acc.x + h.x) + __ldg(&b2[0]),
                        dv * (acc.y + h.y) + __ldg(&b2[1]));
}

// ---------------- launch ----------------
extern "C" void kernel_launch(void* const* d_in, const int* in_sizes, int n_in,
                              void* d_out, int out_size) {
    const float* x  = (const float*)d_in[0];   // [N, 3] f32
    const int*   ei = (const int*)d_in[1];     // [2, E] int32
    const float* W1 = (const float*)d_in[2];   // [3, 8]
    const float* b1 = (const float*)d_in[3];   // [8]
    const float* W2 = (const float*)d_in[4];   // [8, 2]
    const float* b2 = (const float*)d_in[5];   // [2]
    float* out = (float*)d_out;                // [N, 2] f32

    const int TB = 256;
    const int gN  = (N_NODES + TB - 1) / TB;
    const int gE8 = (N_EDGES / 8 + TB - 1) / TB;

    k_init_deg<<<gN, TB>>>();
    k_degree  <<<gE8, TB>>>(ei);
    k_node1   <<<gN, TB>>>(x);
    k_edge1   <<<gE8, TB>>>(ei);
    k_node2   <<<gN, TB>>>(W1, b1, W2, out);
    k_edge2   <<<gE8, TB>>>(ei, out);
    k_fin     <<<gN, TB>>>(b2, out);
}

// round 10
// speedup vs baseline: 1.2376x; 1.0112x over previous
#include <cuda_runtime.h>
#include <cstdint>

// Problem constants (from reference_code)
#define N_NODES 500000
#define N_EDGES 8000000

// ---------------- scratch (device globals: allocation-free) ----------------
// Layer-1 aggregation in 3-dim input space (linearity of x@W1):
//   out1[d] = dinv[d] * (sum_s xs[s] + xs[d]) @ W1 + b1,  xs = x * dinv
__device__ __align__(16) float4 g_xs  [N_NODES];   // (x*dinv, pad) 8 MB, L2-resident
__device__ __align__(16) float4 g_acc [N_NODES];   // layer-1 scatter accumulator, 8 MB
__device__ __align__(8)  float  g_hs2 [N_NODES*2]; // layer-2 scaled features, 4 MB
__device__               float  g_dinv[N_NODES];   // rsqrt(deg)
__device__               int    g_cnt [N_NODES];   // in-degree histogram (self-cleaning)

// ---------------- kernels ----------------

// dst histogram (int), 4 edges/thread. g_cnt starts zero (bss) and is re-zeroed
// by k_node1 every call, so graph replays are deterministic.
__global__ void __launch_bounds__(256) k_hist(const int* __restrict__ ei) {
    int i = blockIdx.x * blockDim.x + threadIdx.x;
    if (i >= N_EDGES / 4) return;
    int4 d4 = __ldg(reinterpret_cast<const int4*>(ei + N_EDGES) + i);
    atomicAdd(&g_cnt[d4.x], 1);
    atomicAdd(&g_cnt[d4.y], 1);
    atomicAdd(&g_cnt[d4.z], 1);
    atomicAdd(&g_cnt[d4.w], 1);
}

// dinv = rsqrt(cnt + 1 self-loop); xs = x * dinv; acc = 0; reset cnt
__global__ void k_node1(const float* __restrict__ x) {
    int i = blockIdx.x * blockDim.x + threadIdx.x;
    if (i >= N_NODES) return;
    float dv = rsqrtf((float)g_cnt[i] + 1.0f);
    g_cnt[i] = 0;                       // self-clean for next graph replay
    g_dinv[i] = dv;
    float x0 = x[3 * i], x1 = x[3 * i + 1], x2 = x[3 * i + 2];
    g_xs [i] = make_float4(x0 * dv, x1 * dv, x2 * dv, 0.f);
    g_acc[i] = make_float4(0.f, 0.f, 0.f, 0.f);
}

#define RED4(ptr, v) \
    asm volatile("red.global.add.v4.f32 [%0], {%1,%2,%3,%4};" \
                 :: "l"(ptr), "f"((v).x), "f"((v).y), "f"((v).z), "f"((v).w) : "memory")
#define RED2(ptr, v) \
    asm volatile("red.global.add.v2.f32 [%0], {%1,%2};" \
                 :: "l"(ptr), "f"((v).x), "f"((v).y) : "memory")

// acc[dst] += xs[src]; 4 edges/thread. Blocks iterate REVERSED so this pass
// starts at the index-array tail, which k_hist touched most recently (L2 hit).
__global__ void __launch_bounds__(256) k_edge1(const int* __restrict__ ei) {
    int blk = gridDim.x - 1 - blockIdx.x;                 // reversed block order
    int i = blk * blockDim.x + threadIdx.x;
    if (i >= N_EDGES / 4) return;
    int4 s4 = __ldg(reinterpret_cast<const int4*>(ei) + i);
    int4 d4 = __ldg(reinterpret_cast<const int4*>(ei + N_EDGES) + i);
    float4 v0 = __ldg(&g_xs[s4.x]);
    float4 v1 = __ldg(&g_xs[s4.y]);
    float4 v2 = __ldg(&g_xs[s4.z]);
    float4 v3 = __ldg(&g_xs[s4.w]);
    RED4(&g_acc[d4.x], v0);
    RED4(&g_acc[d4.y], v1);
    RED4(&g_acc[d4.z], v2);
    RED4(&g_acc[d4.w], v3);
}

// t = dinv*(acc + xs); a = relu(t@W1 + b1); hs2 = (a@W2)*dinv; out = 0
__global__ void k_node2(const float* __restrict__ W1, const float* __restrict__ b1,
                        const float* __restrict__ W2, float* __restrict__ out) {
    int i = blockIdx.x * blockDim.x + threadIdx.x;
    if (i >= N_NODES) return;
    float dv = g_dinv[i];
    float4 xs = g_xs[i];
    float4 ac = g_acc[i];
    float t0 = dv * (ac.x + xs.x);
    float t1 = dv * (ac.y + xs.y);
    float t2 = dv * (ac.z + xs.z);
    float a[8];
#pragma unroll
    for (int j = 0; j < 8; j++) {
        float v = t0 * __ldg(&W1[j]) + t1 * __ldg(&W1[8 + j]) + t2 * __ldg(&W1[16 + j])
                  + __ldg(&b1[j]);
        a[j] = fmaxf(v, 0.0f);
    }
    float o0 = 0.f, o1 = 0.f;
#pragma unroll
    for (int j = 0; j < 8; j++) {
        o0 += a[j] * __ldg(&W2[2 * j]);
        o1 += a[j] * __ldg(&W2[2 * j + 1]);
    }
    reinterpret_cast<float2*>(&g_hs2[(size_t)i * 2])[0] = make_float2(o0 * dv, o1 * dv);
    reinterpret_cast<float2*>(&out[(size_t)i * 2])[0]   = make_float2(0.f, 0.f);
}

// out[dst] += hs2[src]; forward order (edge1-reversed left the array head freshest)
__global__ void __launch_bounds__(256) k_edge2(const int* __restrict__ ei,
                                               float* __restrict__ out) {
    int i = blockIdx.x * blockDim.x + threadIdx.x;
    if (i >= N_EDGES / 4) return;
    int4 s4 = __ldg(reinterpret_cast<const int4*>(ei) + i);
    int4 d4 = __ldg(reinterpret_cast<const int4*>(ei + N_EDGES) + i);
    const float2* hs = reinterpret_cast<const float2*>(g_hs2);
    float2 v0 = __ldg(hs + s4.x);
    float2 v1 = __ldg(hs + s4.y);
    float2 v2 = __ldg(hs + s4.z);
    float2 v3 = __ldg(hs + s4.w);
    RED2(out + (size_t)d4.x * 2, v0);
    RED2(out + (size_t)d4.y * 2, v1);
    RED2(out + (size_t)d4.z * 2, v2);
    RED2(out + (size_t)d4.w * 2, v3);
}

// out = dinv*(out + hs2) + b2
__global__ void k_fin(const float* __restrict__ b2, float* __restrict__ out) {
    int i = blockIdx.x * blockDim.x + threadIdx.x;
    if (i >= N_NODES) return;
    float dv = g_dinv[i];
    float2* op = reinterpret_cast<float2*>(&out[(size_t)i * 2]);
    float2 acc = op[0];
    const float2 h = reinterpret_cast<const float2*>(&g_hs2[(size_t)i * 2])[0];
    op[0] = make_float2(dv * (acc.x + h.x) + __ldg(&b2[0]),
                        dv * (acc.y + h.y) + __ldg(&b2[1]));
}

// ---------------- launch ----------------
extern "C" void kernel_launch(void* const* d_in, const int* in_sizes, int n_in,
                              void* d_out, int out_size) {
    const float* x  = (const float*)d_in[0];   // [N, 3] f32
    const int*   ei = (const int*)d_in[1];     // [2, E] int32
    const float* W1 = (const float*)d_in[2];   // [3, 8]
    const float* b1 = (const float*)d_in[3];   // [8]
    const float* W2 = (const float*)d_in[4];   // [8, 2]
    const float* b2 = (const float*)d_in[5];   // [2]
    float* out = (float*)d_out;                // [N, 2] f32

    const int TB = 256;
    const int gN  = (N_NODES + TB - 1) / TB;
    const int gE4 = (N_EDGES / 4 + TB - 1) / TB;

    k_hist  <<<gE4, TB>>>(ei);
    k_node1 <<<gN, TB>>>(x);
    k_edge1 <<<gE4, TB>>>(ei);
    k_node2 <<<gN, TB>>>(W1, b1, W2, out);
    k_edge2 <<<gE4, TB>>>(ei, out);
    k_fin   <<<gN, TB>>>(b2, out);
}